// round 4
// baseline (speedup 1.0000x reference)
#include <cuda_runtime.h>
#include <cuda_bf16.h>
#include <cstddef>
#include <cstdint>

#define S_LEN   2048
#define BATCH   32
#define IN_DIM  64
#define EMB_DIM 32
#define HID     256
#define XE      96
#define G4      1024
#define NGRP    16      // batch groups = clusters
#define CSIZE   8       // CTAs per cluster

// ---- device scratch (module globals: the sanctioned scratch mechanism) ----
__device__ float g_zx[(size_t)S_LEN * BATCH * G4];   // [t][b][row], 256 MiB

namespace {
struct EagerLoad {  // force module load before harness mem checkpoints
    EagerLoad() { void* p = nullptr; (void)cudaGetSymbolAddress(&p, g_zx); }
};
static EagerLoad eager_;
}

// ---- fast accurate activations --------------------------------------------
__device__ __forceinline__ float sigf(float x) {
    return __fdividef(1.f, 1.f + __expf(-x));
}
__device__ __forceinline__ float tanh_f(float x) {
    float ax = fabsf(x);
    float e  = __expf(-2.f * ax);            // in (0,1], never overflows
    return copysignf(__fdividef(1.f - e, 1.f + e), x);
}

// ---- f32x2 packed FMA (sm_10x; ptxas never auto-fuses this) ---------------
#define FMA2(d, a, b) \
    asm("fma.rn.f32x2 %0, %1, %2, %0;" : "+l"(d) : "l"(a), "l"(b))

__device__ __forceinline__ float hsum2(unsigned long long v) {
    float lo, hi;
    asm("mov.b64 {%0,%1}, %2;" : "=f"(lo), "=f"(hi) : "l"(v));
    return lo + hi;
}

__device__ __forceinline__ uint32_t smem_u32(const void* p) {
    uint32_t a;
    asm("{ .reg .u64 t; cvta.to.shared.u64 t, %1; cvt.u32.u64 %0, t; }"
        : "=r"(a) : "l"(p));
    return a;
}
// store to the same smem offset in CTA `rank` of this cluster
__device__ __forceinline__ void st_cluster_f32(uint32_t laddr, uint32_t rank, float v) {
    asm volatile(
        "{\n\t.reg .u32 ra;\n\t"
        "mapa.shared::cluster.u32 ra, %0, %1;\n\t"
        "st.shared::cluster.f32 [ra], %2;\n\t}"
        :: "r"(laddr), "r"(rank), "f"(v) : "memory");
}

// ---------------------------------------------------------------------------
// Kernel A: zx[t][b][row] = bias[row] + sum_i [x|emb][b][t][i] * W_ih[row][i]
// grid (16 row-tiles, 2048 t), 256 threads. FFMA2 over k-pairs.
// ---------------------------------------------------------------------------
__global__ void __launch_bounds__(256) zx_kernel(
    const float* __restrict__ x, const float* __restrict__ emb,
    const float* __restrict__ W_ih, const float* __restrict__ bias)
{
    const int t = blockIdx.y, rbase = blockIdx.x * 64, tid = threadIdx.x;

    __shared__ __align__(16) float xe_s[BATCH][100];   // 100*4=400B rows (16B-mult)
    __shared__ __align__(16) float W_s[64][100];

    for (int idx = tid; idx < BATCH * IN_DIM; idx += 256) {
        int b = idx >> 6, i = idx & 63;
        xe_s[b][i] = x[((size_t)b * S_LEN + t) * IN_DIM + i];
    }
    for (int idx = tid; idx < BATCH * EMB_DIM; idx += 256) {
        int b = idx >> 5, i = idx & 31;
        xe_s[b][IN_DIM + i] = emb[((size_t)b * S_LEN + t) * EMB_DIM + i];
    }
    for (int idx = tid; idx < 64 * XE; idx += 256) {
        int r = idx / XE, i = idx - r * XE;
        W_s[r][i] = W_ih[(size_t)(rbase + r) * XE + i];
    }
    __syncthreads();

    const int m = tid & 15, b0 = (tid >> 4) * 2;

    unsigned long long acc[4][2][2];   // [rowslot][batch][pair] as f32x2
#pragma unroll
    for (int j = 0; j < 4; ++j)
#pragma unroll
        for (int b = 0; b < 2; ++b)
            acc[j][b][0] = acc[j][b][1] = 0ull;

    const ulonglong2* xv0 = reinterpret_cast<const ulonglong2*>(&xe_s[b0][0]);
    const ulonglong2* xv1 = reinterpret_cast<const ulonglong2*>(&xe_s[b0 + 1][0]);
#pragma unroll
    for (int k4 = 0; k4 < XE / 4; ++k4) {
        ulonglong2 xa = xv0[k4], xb = xv1[k4];
#pragma unroll
        for (int j = 0; j < 4; ++j) {
            ulonglong2 w = reinterpret_cast<const ulonglong2*>(&W_s[m + 16 * j][0])[k4];
            FMA2(acc[j][0][0], w.x, xa.x);
            FMA2(acc[j][0][1], w.y, xa.y);
            FMA2(acc[j][1][0], w.x, xb.x);
            FMA2(acc[j][1][1], w.y, xb.y);
        }
    }
#pragma unroll
    for (int j = 0; j < 4; ++j) {
        int row = rbase + m + 16 * j;
        float bv = __ldg(&bias[row]);
        size_t base = ((size_t)t * BATCH + b0) * G4 + row;
        g_zx[base]      = hsum2(acc[j][0][0]) + hsum2(acc[j][0][1]) + bv;
        g_zx[base + G4] = hsum2(acc[j][1][0]) + hsum2(acc[j][1][1]) + bv;
    }
}

// ---------------------------------------------------------------------------
// Kernel B: persistent recurrent LSTM on 16 independent 8-CTA clusters.
// Cluster = 2 batches; CTA (rank) owns 32 h-units x all 4 gates.
// W_hh slice smem-resident; h exchanged via DSMEM + cluster barrier.
// ---------------------------------------------------------------------------
__global__ void __launch_bounds__(256, 1) __cluster_dims__(CSIZE, 1, 1)
lstm_kernel(const float* __restrict__ W_hh, float* __restrict__ out)
{
    extern __shared__ __align__(16) float4 Wt[];        // [64 k4][128 r] = 128 KiB
    __shared__ __align__(16) float hb[2][2][HID];       // [buf][batch][k]
    __shared__ __align__(16) float zs[2][128];          // [batch][gate*32+u]

    const int tid  = threadIdx.x;
    const int grp  = blockIdx.x / CSIZE;                // cluster id = batch group
    uint32_t rank;
    asm("mov.u32 %0, %%cluster_ctarank;" : "=r"(rank));
    const int b0 = grp * 2;
    const int u0 = (int)rank * 32;

    // one-time: W_hh rows (gate g, unit u0+uu) transposed into smem
    for (int idx = tid; idx < 128 * 64; idx += 256) {
        int r = idx >> 6, k4 = idx & 63;
        int g = r >> 5, uu = r & 31;
        const float4* src = reinterpret_cast<const float4*>(
            W_hh + (size_t)(g * HID + u0 + uu) * HID);
        Wt[k4 * 128 + r] = src[k4];
    }
    __syncthreads();

    const int r  = tid & 127;                 // row: gate g=r>>5, unit uu=r&31
    const int gg = r >> 5, uu = r & 31;
    const size_t zxoff = (size_t)gg * HID + u0 + uu;

    float c_reg = 0.f;                        // cell state lives in registers
    const int gb = b0 + (tid >> 5);           // gates mapping (tid<64)
    const int gu = u0 + (tid & 31);

    for (int t = 0; t < S_LEN; ++t) {
        // prefetch zx (DRAM latency hides under the dot)
        float zxa = 0.f, zxb = 0.f;
        if (tid < 128) {
            const float* zp = g_zx + ((size_t)t * BATCH + b0) * G4 + zxoff;
            zxa = __ldcs(zp);
            zxb = __ldcs(zp + G4);
        }

        if (t > 0) {
            // dot: z[r][b] = sum_k Wt[k][r] * h[b][k], FFMA2 over k-pairs
            unsigned long long a0 = 0ull, a1 = 0ull, a2 = 0ull, a3 = 0ull;
            if (tid < 128) {
                const int buf = (t - 1) & 1;
                const ulonglong2* h0 = reinterpret_cast<const ulonglong2*>(hb[buf][0]);
                const ulonglong2* h1 = reinterpret_cast<const ulonglong2*>(hb[buf][1]);
                const ulonglong2* wp = reinterpret_cast<const ulonglong2*>(Wt) + r;
#pragma unroll 16
                for (int k4 = 0; k4 < 64; ++k4) {
                    ulonglong2 w = wp[k4 * 128];
                    ulonglong2 p = h0[k4];
                    ulonglong2 q = h1[k4];
                    FMA2(a0, w.x, p.x);
                    FMA2(a1, w.y, p.y);
                    FMA2(a2, w.x, q.x);
                    FMA2(a3, w.y, q.y);
                }
                zs[0][r] = zxa + hsum2(a0) + hsum2(a1);
                zs[1][r] = zxb + hsum2(a2) + hsum2(a3);
            }
        } else if (tid < 128) {
            zs[0][r] = zxa;                   // h(-1) = 0
            zs[1][r] = zxb;
        }
        __syncthreads();

        if (tid < 64) {
            const int b = tid >> 5, u = tid & 31;
            const float* z = zs[b];
            float zi = z[u], zf = z[32 + u], zg = z[64 + u], zo = z[96 + u];
            float c = sigf(zf) * c_reg + sigf(zi) * tanh_f(zg);
            float h = sigf(zo) * tanh_f(c);
            c_reg = c;

            out[((size_t)gb * S_LEN + t) * HID + gu] = h;
            if (t == S_LEN - 1) {
                size_t tail = (size_t)BATCH * S_LEN * HID;
                out[tail + gb * HID + gu] = h;                 // final h
                out[tail + BATCH * HID + gb * HID + gu] = c;   // final c
            }

            // scatter h(t) into hb[t&1] of every CTA in the cluster (incl self)
            uint32_t laddr = smem_u32(&hb[t & 1][b][gu]);
#pragma unroll
            for (uint32_t pr = 0; pr < CSIZE; ++pr)
                st_cluster_f32(laddr, pr, h);
        }

        // release own stores / acquire peers' (arrive=release, wait=acquire)
        asm volatile("barrier.cluster.arrive.aligned;" ::: "memory");
        asm volatile("barrier.cluster.wait.aligned;"   ::: "memory");
    }
}

// ---------------------------------------------------------------------------
extern "C" void kernel_launch(void* const* d_in, const int* in_sizes, int n_in,
                              void* d_out, int out_size) {
    const float* x    = (const float*)d_in[0];
    const float* emb  = (const float*)d_in[1];
    const float* W_ih = (const float*)d_in[2];
    const float* W_hh = (const float*)d_in[3];
    const float* bias = (const float*)d_in[4];
    float* out = (float*)d_out;

    const int smem = 64 * 128 * sizeof(float4);   // 128 KiB dynamic (Wt)
    static bool attr_set = false;
    if (!attr_set) {
        cudaFuncSetAttribute(lstm_kernel,
                             cudaFuncAttributeMaxDynamicSharedMemorySize, smem);
        attr_set = true;
    }

    zx_kernel<<<dim3(16, S_LEN), 256>>>(x, emb, W_ih, bias);
    lstm_kernel<<<NGRP * CSIZE, 256, smem>>>(W_hh, out);
}